// round 15
// baseline (speedup 1.0000x reference)
#include <cuda_runtime.h>
#include <cstdint>
#include <cstddef>

#define Bb  4
#define Ss  2048
#define Dd  512
#define Hh  8
#define DHh 64
#define Nn  (Bb*Ss)

typedef unsigned long long u64;

// ---------------- device scratch ----------------
__device__ float g_Qt[Bb*Hh*DHh*Ss];    // [bh][d][s]
__device__ float g_Kt[Bb*Hh*DHh*Ss];    // [bh][d][s]
__device__ float g_V [Bb*Hh*Ss*DHh];    // [bh][s][d]
__device__ float g_ctx[(size_t)Nn*Dd];  // [b*s][d]
__device__ float g_meanV[Bb*Hh*DHh];    // [bh][d]

// ---------------- f32x2 helpers ----------------
__device__ __forceinline__ u64 pack2(float x, float y) {
  u64 r;
  asm("mov.b64 %0, {%1, %2};" : "=l"(r)
      : "r"(__float_as_uint(x)), "r"(__float_as_uint(y)));
  return r;
}
__device__ __forceinline__ u64 bcast2(float x) { return pack2(x, x); }
__device__ __forceinline__ float2 unpack2(u64 v) {
  unsigned a, b;
  asm("mov.b64 {%0, %1}, %2;" : "=r"(a), "=r"(b) : "l"(v));
  return make_float2(__uint_as_float(a), __uint_as_float(b));
}
__device__ __forceinline__ void ffma2(u64 &d, u64 a, u64 b) {
  asm("fma.rn.f32x2 %0, %1, %2, %0;" : "+l"(d) : "l"(a), "l"(b));
}
__device__ __forceinline__ void fmul2(u64 &d, u64 a) {
  asm("mul.rn.f32x2 %0, %0, %1;" : "+l"(d) : "l"(a));
}

// ---------------- 128x128 tile GEMM over K=512, f32x2 ---------------------
// 256 threads (16x16), 8x8 microtile, acc pairs along m. K-slab 16 with
// register prefetch. As stored [k][m] (transposed scatter) so a-pairs come
// straight out of LDS.128.
#define ASTRIDE 132

__device__ __forceinline__ void gemm128(const float* __restrict__ A,
                                        const float* __restrict__ W,
                                        int m0, int n0,
                                        u64 (&acc)[4][8],
                                        float* As, float* Bs) {
  const int tid = threadIdx.x;
  const int ty = tid >> 4, tx = tid & 15;
  const int a_k4 = tid & 3;          // k-group (4 floats)
  const int a_m  = tid >> 2;         // 0..63 (+64*r)
  const int b_n4 = tid & 31;         // 0..31
  const int b_k  = tid >> 5;         // 0..7 (+8*r)

  float4 pa[2], pb[2];
#pragma unroll
  for (int r = 0; r < 2; r++) {
    pa[r] = *(const float4*)&A[(size_t)(m0 + a_m + 64*r)*Dd + a_k4*4];
    pb[r] = *(const float4*)&W[(size_t)(b_k + 8*r)*Dd + n0 + b_n4*4];
  }

  for (int kb = 0; kb < Dd; kb += 16) {
    // scatter-store prefetched slab
#pragma unroll
    for (int r = 0; r < 2; r++) {
      float* ad = &As[(a_k4*4)*ASTRIDE + a_m + 64*r];
      ad[0*ASTRIDE] = pa[r].x; ad[1*ASTRIDE] = pa[r].y;
      ad[2*ASTRIDE] = pa[r].z; ad[3*ASTRIDE] = pa[r].w;
      *(float4*)&Bs[(b_k + 8*r)*ASTRIDE + b_n4*4] = pb[r];
    }
    __syncthreads();
    if (kb + 16 < Dd) {
#pragma unroll
      for (int r = 0; r < 2; r++) {
        pa[r] = *(const float4*)&A[(size_t)(m0 + a_m + 64*r)*Dd + kb + 16 + a_k4*4];
        pb[r] = *(const float4*)&W[(size_t)(kb + 16 + b_k + 8*r)*Dd + n0 + b_n4*4];
      }
    }
#pragma unroll 4
    for (int kk = 0; kk < 16; kk++) {
      float4 a0 = *(const float4*)&As[kk*ASTRIDE + ty*8];
      float4 a1 = *(const float4*)&As[kk*ASTRIDE + ty*8 + 4];
      float4 b0 = *(const float4*)&Bs[kk*ASTRIDE + tx*8];
      float4 b1 = *(const float4*)&Bs[kk*ASTRIDE + tx*8 + 4];
      u64 ap[4] = { pack2(a0.x, a0.y), pack2(a0.z, a0.w),
                    pack2(a1.x, a1.y), pack2(a1.z, a1.w) };
      u64 bp[8] = { bcast2(b0.x), bcast2(b0.y), bcast2(b0.z), bcast2(b0.w),
                    bcast2(b1.x), bcast2(b1.y), bcast2(b1.z), bcast2(b1.w) };
#pragma unroll
      for (int mp = 0; mp < 4; mp++)
#pragma unroll
        for (int j = 0; j < 8; j++) ffma2(acc[mp][j], ap[mp], bp[j]);
    }
    __syncthreads();
  }
}

// ---------------- QKV projection ------------------------------------------
__global__ __launch_bounds__(256, 2)
void proj_kernel(const float* __restrict__ X,
                 const float* __restrict__ Wq,
                 const float* __restrict__ Wk,
                 const float* __restrict__ Wv) {
  __shared__ __align__(16) float As[16*ASTRIDE];
  __shared__ __align__(16) float Bs[16*ASTRIDE];
  const int z = blockIdx.z;
  const float* W = (z == 0) ? Wq : ((z == 1) ? Wk : Wv);
  const int m0 = blockIdx.x * 128, n0 = blockIdx.y * 128;
  u64 acc[4][8] = {};
  gemm128(X, W, m0, n0, acc, As, Bs);

  const int tid = threadIdx.x, ty = tid >> 4, tx = tid & 15;
  const int b  = m0 >> 11;
  const int s0 = m0 & (Ss - 1);
  if (z == 2) {
    const int nb = n0 + tx*8;
    const int bh = b*Hh + (nb >> 6);
    const int d0 = nb & 63;   // 8-wide chunk never straddles a head
#pragma unroll
    for (int i = 0; i < 8; i++) {
      const int mp = i >> 1, half = i & 1;
      float v[8];
#pragma unroll
      for (int j = 0; j < 8; j++) {
        float2 p = unpack2(acc[mp][j]);
        v[j] = half ? p.y : p.x;
      }
      float* dst = &g_V[((size_t)bh*Ss + s0 + ty*8 + i)*DHh + d0];
      *(float4*)dst       = make_float4(v[0], v[1], v[2], v[3]);
      *(float4*)(dst + 4) = make_float4(v[4], v[5], v[6], v[7]);
    }
  } else {
    float* dstA = (z == 0) ? g_Qt : g_Kt;
#pragma unroll
    for (int j = 0; j < 8; j++) {
      const int nb = n0 + tx*8 + j;
      const int bh = b*Hh + (nb >> 6);
      const int dd = nb & 63;
      float2 p0 = unpack2(acc[0][j]);
      float2 p1 = unpack2(acc[1][j]);
      float2 p2 = unpack2(acc[2][j]);
      float2 p3 = unpack2(acc[3][j]);
      float* dst = &dstA[((size_t)bh*DHh + dd)*Ss + s0 + ty*8];
      *(float4*)dst       = make_float4(p0.x, p0.y, p1.x, p1.y);
      *(float4*)(dst + 4) = make_float4(p2.x, p2.y, p3.x, p3.y);
    }
  }
}

// ---------------- mean of V (masked-query fallback) ------------------------
__global__ void meanv_kernel() {
  __shared__ float red[1024];
  const int bh = blockIdx.x, t = threadIdx.x;
  const int d = t & 63, c = t >> 6;           // 16 chunks of 128 keys
  const float* vp = &g_V[((size_t)bh*Ss + c*128)*DHh + d];
  float sum = 0.f;
#pragma unroll 4
  for (int s = 0; s < 128; s++) sum += vp[(size_t)s*DHh];
  red[t] = sum;
  __syncthreads();
  if (t < 64) {
    float a = 0.f;
#pragma unroll
    for (int c2 = 0; c2 < 16; c2++) a += red[c2*64 + t];
    g_meanV[bh*DHh + t] = a * (1.f/2048.f);
  }
}

// ---------------- causal flash attention, f32x2 ----------------------------
// 128q x 64k tiles, 256 threads, 8x4 microtile (q-pairs free).
// smem: Qs[64][132] Ks[64][68] Vs[64][68] Pt[64][132] tmk[64]
#define FL_QS   0
#define FL_KS   (64*132)
#define FL_VS   (FL_KS + 64*68)
#define FL_PT   (FL_VS + 64*68)
#define FL_TMK  (FL_PT + 64*132)
#define FLASH_SMEM_BYTES ((FL_TMK + 64)*4)

__global__ __launch_bounds__(256, 2)
void flash_kernel(const int* __restrict__ tm) {
  extern __shared__ __align__(16) float sm[];
  float* Qs  = sm + FL_QS;
  float* Ks  = sm + FL_KS;
  float* Vs  = sm + FL_VS;
  float* Pt  = sm + FL_PT;
  float* tmk = sm + FL_TMK;

  const int bh = blockIdx.y, b = bh >> 3, h = bh & 7;
  const int qt = (int)gridDim.x - 1 - (int)blockIdx.x;  // heavy first
  const int q0 = qt * 128;
  const int tid = threadIdx.x, ty = tid >> 4, tx = tid & 15;

  // load Q tile [d=64][q=128]
#pragma unroll
  for (int r = 0; r < 8; r++) {
    const int idx = tid + 256*r;
    const int d = idx >> 5, q4 = idx & 31;
    *(float4*)&Qs[d*132 + q4*4] =
        *(const float4*)&g_Qt[((size_t)bh*DHh + d)*Ss + q0 + q4*4];
  }
  int tmq[8];
#pragma unroll
  for (int i = 0; i < 8; i++) tmq[i] = tm[b*Ss + q0 + ty*8 + i];

  u64 o[4][4] = {};
  float mi[8], li[8];
#pragma unroll
  for (int i = 0; i < 8; i++) { mi[i] = -1e30f; li[i] = 0.f; }

  const int KT = 2*qt + 1;
  for (int kt = 0; kt <= KT; kt++) {
    __syncthreads();
    const int k0 = kt * 64;
#pragma unroll
    for (int r = 0; r < 4; r++) {
      const int idx = tid + 256*r;
      const int rowk = idx >> 4, c4 = idx & 15;
      *(float4*)&Ks[rowk*68 + c4*4] =
          *(const float4*)&g_Kt[((size_t)bh*DHh + rowk)*Ss + k0 + c4*4];
      *(float4*)&Vs[rowk*68 + c4*4] =
          *(const float4*)&g_V[((size_t)bh*Ss + k0 + rowk)*DHh + c4*4];
    }
    if (tid < 64) tmk[tid] = (float)tm[b*Ss + k0 + tid];
    __syncthreads();

    // S = Q K^T : 8q x 4k per thread, pairs along q
    u64 s[4][4] = {};
#pragma unroll 4
    for (int d = 0; d < 64; d++) {
      float4 a0 = *(const float4*)&Qs[d*132 + ty*8];
      float4 a1 = *(const float4*)&Qs[d*132 + ty*8 + 4];
      float4 kv = *(const float4*)&Ks[d*68 + tx*4];
      u64 ap[4] = { pack2(a0.x, a0.y), pack2(a0.z, a0.w),
                    pack2(a1.x, a1.y), pack2(a1.z, a1.w) };
      u64 bp[4] = { bcast2(kv.x), bcast2(kv.y), bcast2(kv.z), bcast2(kv.w) };
#pragma unroll
      for (int mp = 0; mp < 4; mp++)
#pragma unroll
        for (int j = 0; j < 4; j++) ffma2(s[mp][j], ap[mp], bp[j]);
    }

    float tk[4];
#pragma unroll
    for (int j = 0; j < 4; j++) tk[j] = tmk[tx*4 + j];

    // online softmax, 8 rows per thread, 16-lane reductions
    float p[8][4], corr[8];
#pragma unroll
    for (int i = 0; i < 8; i++) {
      const int mp = i >> 1, half = i & 1;
      const int qg = q0 + ty*8 + i;
      float sv[4], rmax = -1e30f;
#pragma unroll
      for (int j = 0; j < 4; j++) {
        float2 pr = unpack2(s[mp][j]);
        const float val = half ? pr.y : pr.x;
        const int kg = k0 + tx*4 + j;
        const bool valid = (kg <= qg) && (tk[j] > 0.5f);
        sv[j] = valid ? val * 0.125f : -1e30f;
        rmax = fmaxf(rmax, sv[j]);
      }
#pragma unroll
      for (int off = 1; off < 16; off <<= 1)
        rmax = fmaxf(rmax, __shfl_xor_sync(0xffffffffu, rmax, off));
      const float mnew = fmaxf(mi[i], rmax);
      float rsum = 0.f;
#pragma unroll
      for (int j = 0; j < 4; j++) {
        p[i][j] = (sv[j] > -1e29f) ? __expf(sv[j] - mnew) : 0.f;
        rsum += p[i][j];
      }
#pragma unroll
      for (int off = 1; off < 16; off <<= 1)
        rsum += __shfl_xor_sync(0xffffffffu, rsum, off);
      corr[i] = __expf(mi[i] - mnew);
      li[i] = li[i] * corr[i] + rsum;
      mi[i] = mnew;
    }
    // rescale O
#pragma unroll
    for (int mp = 0; mp < 4; mp++) {
      u64 cp = pack2(corr[2*mp], corr[2*mp + 1]);
#pragma unroll
      for (int j = 0; j < 4; j++) fmul2(o[mp][j], cp);
    }
    // stage P transposed [k][q]
#pragma unroll
    for (int j = 0; j < 4; j++) {
      float* dst = &Pt[(tx*4 + j)*132 + ty*8];
      *(float4*)dst       = make_float4(p[0][j], p[1][j], p[2][j], p[3][j]);
      *(float4*)(dst + 4) = make_float4(p[4][j], p[5][j], p[6][j], p[7][j]);
    }
    __syncthreads();

    // O += P V : pairs along q
#pragma unroll 4
    for (int k = 0; k < 64; k++) {
      float4 a0 = *(const float4*)&Pt[k*132 + ty*8];
      float4 a1 = *(const float4*)&Pt[k*132 + ty*8 + 4];
      float4 vv = *(const float4*)&Vs[k*68 + tx*4];
      u64 ap[4] = { pack2(a0.x, a0.y), pack2(a0.z, a0.w),
                    pack2(a1.x, a1.y), pack2(a1.z, a1.w) };
      u64 bp[4] = { bcast2(vv.x), bcast2(vv.y), bcast2(vv.z), bcast2(vv.w) };
#pragma unroll
      for (int mp = 0; mp < 4; mp++)
#pragma unroll
        for (int j = 0; j < 4; j++) ffma2(o[mp][j], ap[mp], bp[j]);
    }
  }

  // epilogue
#pragma unroll
  for (int i = 0; i < 8; i++) {
    const int mp = i >> 1, half = i & 1;
    const int srow = q0 + ty*8 + i;
    float4 res;
    if (tmq[i] != 0) {
      const float inv = 1.f / li[i];
      float v[4];
#pragma unroll
      for (int j = 0; j < 4; j++) {
        float2 pr = unpack2(o[mp][j]);
        v[j] = (half ? pr.y : pr.x) * inv;
      }
      res = make_float4(v[0], v[1], v[2], v[3]);
    } else {
      res = *(const float4*)&g_meanV[bh*DHh + tx*4];
    }
    *(float4*)&g_ctx[((size_t)b*Ss + srow)*Dd + h*DHh + tx*4] = res;
  }
}

// ---------------- output projection ---------------------------------------
__global__ __launch_bounds__(256, 2)
void outproj_kernel(const float* __restrict__ Wo, float* __restrict__ out) {
  __shared__ __align__(16) float As[16*ASTRIDE];
  __shared__ __align__(16) float Bs[16*ASTRIDE];
  const int m0 = blockIdx.x * 128, n0 = blockIdx.y * 128;
  u64 acc[4][8] = {};
  gemm128(g_ctx, Wo, m0, n0, acc, As, Bs);
  const int tid = threadIdx.x, ty = tid >> 4, tx = tid & 15;
#pragma unroll
  for (int i = 0; i < 8; i++) {
    const int mp = i >> 1, half = i & 1;
    float v[8];
#pragma unroll
    for (int j = 0; j < 8; j++) {
      float2 p = unpack2(acc[mp][j]);
      v[j] = half ? p.y : p.x;
    }
    float* dst = &out[(size_t)(m0 + ty*8 + i)*Dd + n0 + tx*8];
    *(float4*)dst       = make_float4(v[0], v[1], v[2], v[3]);
    *(float4*)(dst + 4) = make_float4(v[4], v[5], v[6], v[7]);
  }
}

// ---------------- launch ---------------------------------------------------
extern "C" void kernel_launch(void* const* d_in, const int* in_sizes, int n_in,
                              void* d_out, int out_size) {
  (void)in_sizes; (void)n_in; (void)out_size;
  const float* emb = (const float*)d_in[0];
  const int*   tm  = (const int*)  d_in[1];
  const float* Wq  = (const float*)d_in[2];
  const float* Wk  = (const float*)d_in[3];
  const float* Wv  = (const float*)d_in[4];
  const float* Wo  = (const float*)d_in[5];
  float* out = (float*)d_out;

  cudaFuncSetAttribute(flash_kernel,
                       cudaFuncAttributeMaxDynamicSharedMemorySize,
                       FLASH_SMEM_BYTES);

  proj_kernel<<<dim3(Nn/128, Dd/128, 3), 256>>>(emb, Wq, Wk, Wv);
  meanv_kernel<<<Bb*Hh, 1024>>>();
  flash_kernel<<<dim3(Ss/128, Bb*Hh), 256, FLASH_SMEM_BYTES>>>(tm);
  outproj_kernel<<<dim3(Nn/128, Dd/128), 256>>>(Wo, out);
}